// round 16
// baseline (speedup 1.0000x reference)
#include <cuda_runtime.h>
#include <cuda_bf16.h>

// ---------------- problem constants (fixed shapes) ----------------
#define N_SRC1 200000
#define N_DST1 50000
#define N_DST2 10000
#define E1     2000000
#define E2     400000
#define IN_F   128
#define H_F    256
#define N_CLS  47

#define PAD1   50048   // N_DST1 padded to multiple of 128
#define PN     48      // padded layer-2 projected width

// ---------------- scratch (device globals; zero-initialized) ----------------
__device__ int   g_is64;
__device__ int   g_off1[N_DST1 + 1];
__device__ int   g_off2[N_DST2 + 1];
__device__ float g_h[(size_t)PAD1 * H_F];          // layer1 output (relu'd)
__device__ float g_p[(size_t)PAD1 * PN];           // h @ Wneigh2 (projected, padded)
__device__ float g_pagg[(size_t)N_DST2 * PN];      // mean-aggregated p
// layer-1 A operand, concat along k (0-127: x, 128-255: hneigh1), bf16 hi/lo
__device__ __align__(16) unsigned short g_acat_hi[(size_t)PAD1 * 256];
__device__ __align__(16) unsigned short g_acat_lo[(size_t)PAD1 * 256];
// layer-1 W concat transposed to [n=256][k=256], bf16 hi/lo
__device__ __align__(16) unsigned short g_bt_hi[256 * 256];
__device__ __align__(16) unsigned short g_bt_lo[256 * 256];
// layer-2 weights transposed to [n=64 pad][k=256], bf16 hi/lo
__device__ __align__(16) unsigned short g_w2n_hi[64 * 256];
__device__ __align__(16) unsigned short g_w2n_lo[64 * 256];
__device__ __align__(16) unsigned short g_w2s_hi[64 * 256];
__device__ __align__(16) unsigned short g_w2s_lo[64 * 256];

// ---------------- helpers ----------------
__device__ __forceinline__ unsigned smem_u32(const void* p) {
    unsigned a;
    asm("{ .reg .u64 t; cvta.to.shared.u64 t, %1; cvt.u32.u64 %0, t; }"
        : "=r"(a) : "l"(p));
    return a;
}
__device__ __forceinline__ void ldsm_x4(unsigned* r, unsigned addr) {
    asm volatile("ldmatrix.sync.aligned.m8n8.x4.shared.b16 {%0,%1,%2,%3}, [%4];"
                 : "=r"(r[0]), "=r"(r[1]), "=r"(r[2]), "=r"(r[3]) : "r"(addr));
}
__device__ __forceinline__ void mma_bf16(float* c, const unsigned* a,
                                         unsigned b0, unsigned b1) {
    asm volatile(
        "mma.sync.aligned.m16n8k16.row.col.f32.bf16.bf16.f32 "
        "{%0,%1,%2,%3}, {%4,%5,%6,%7}, {%8,%9}, {%0,%1,%2,%3};"
        : "+f"(c[0]), "+f"(c[1]), "+f"(c[2]), "+f"(c[3])
        : "r"(a[0]), "r"(a[1]), "r"(a[2]), "r"(a[3]), "r"(b0), "r"(b1));
}
__device__ __forceinline__ void cvt4(const float4& f, uint2& h, uint2& l) {
    __nv_bfloat16 h0 = __float2bfloat16(f.x), h1 = __float2bfloat16(f.y);
    __nv_bfloat16 h2 = __float2bfloat16(f.z), h3 = __float2bfloat16(f.w);
    __nv_bfloat16 l0 = __float2bfloat16(f.x - __bfloat162float(h0));
    __nv_bfloat16 l1 = __float2bfloat16(f.y - __bfloat162float(h1));
    __nv_bfloat16 l2 = __float2bfloat16(f.z - __bfloat162float(h2));
    __nv_bfloat16 l3 = __float2bfloat16(f.w - __bfloat162float(h3));
    h.x = (unsigned)__bfloat16_as_ushort(h0) | ((unsigned)__bfloat16_as_ushort(h1) << 16);
    h.y = (unsigned)__bfloat16_as_ushort(h2) | ((unsigned)__bfloat16_as_ushort(h3) << 16);
    l.x = (unsigned)__bfloat16_as_ushort(l0) | ((unsigned)__bfloat16_as_ushort(l1) << 16);
    l.y = (unsigned)__bfloat16_as_ushort(l2) | ((unsigned)__bfloat16_as_ushort(l3) << 16);
}
#define CP16(dst, src) \
    asm volatile("cp.async.ca.shared.global [%0], [%1], 16;" \
                 :: "r"(dst), "l"(src) : "memory")
#define CP_COMMIT() asm volatile("cp.async.commit_group;" ::: "memory")
#define CP_WAIT2()  asm volatile("cp.async.wait_group 2;" ::: "memory")

// ---------------- index dtype detection ----------------
// src1 values are uniform-random in [0, 200000). If int64, every odd 32-bit
// word (high word) is zero; if int32, odd words are random and essentially
// surely nonzero among 128 samples.
__global__ void detect_kernel(const int* __restrict__ src1_raw) {
    if (threadIdx.x == 0) {
        int nz = 0;
        for (int i = 1; i < 256; i += 2) nz |= (src1_raw[i] != 0);
        g_is64 = nz ? 0 : 1;
    }
}

// ---------------- CSR offsets via boundary scatter, 4 edges/thread ----------------
__device__ __forceinline__ void scatter4(const void* dst, int* off, int E,
                                         int ndst, int i, int is64) {
    int base = i * 4;
    int p;
    if (is64) p = (base == 0) ? -1 : (int)((const long long*)dst)[base - 1];
    else      p = (base == 0) ? -1 : ((const int*)dst)[base - 1];
    #pragma unroll
    for (int j = 0; j < 4; ++j) {
        int d = is64 ? (int)((const long long*)dst)[base + j]
                     : ((const int*)dst)[base + j];
        for (int t = p + 1; t <= d; ++t) off[t] = base + j;
        p = d;
    }
    if (base + 4 == E)
        for (int t = p + 1; t <= ndst; ++t) off[t] = E;
}

__global__ void offsets_kernel(const void* __restrict__ dst1,
                               const void* __restrict__ dst2) {
    int i = blockIdx.x * blockDim.x + threadIdx.x;   // E1/4 and E2/4 are exact
    int is64 = g_is64;
    if (i < E1 / 4) scatter4(dst1, g_off1, E1, N_DST1, i, is64);
    if (i < E2 / 4) scatter4(dst2, g_off2, E2, N_DST2, i, is64);
}

// ---------------- W preps: transpose + bf16 hi/lo split ----------------
__global__ void wsplit_kernel(const float* __restrict__ Ws,
                              const float* __restrict__ Wn) {
    int n = blockIdx.x;          // 0..255
    int k = threadIdx.x;         // 0..255
    float v = (k < 128) ? Ws[k * H_F + n] : Wn[(k - 128) * H_F + n];
    __nv_bfloat16 hb = __float2bfloat16(v);
    __nv_bfloat16 lb = __float2bfloat16(v - __bfloat162float(hb));
    g_bt_hi[n * 256 + k] = __bfloat16_as_ushort(hb);
    g_bt_lo[n * 256 + k] = __bfloat16_as_ushort(lb);
}

__global__ void wsplit2_kernel(const float* __restrict__ Wn2,
                               const float* __restrict__ Ws2) {
    int n = blockIdx.x;                      // 0..63 (pad cols 47..63 -> 0)
    int k = blockIdx.y * 64 + threadIdx.x;   // 0..255
    float vn = (n < N_CLS) ? Wn2[k * N_CLS + n] : 0.f;
    float vs = (n < N_CLS) ? Ws2[k * N_CLS + n] : 0.f;
    __nv_bfloat16 nh = __float2bfloat16(vn);
    __nv_bfloat16 nl = __float2bfloat16(vn - __bfloat162float(nh));
    __nv_bfloat16 sh = __float2bfloat16(vs);
    __nv_bfloat16 sl = __float2bfloat16(vs - __bfloat162float(sh));
    g_w2n_hi[n * 256 + k] = __bfloat16_as_ushort(nh);
    g_w2n_lo[n * 256 + k] = __bfloat16_as_ushort(nl);
    g_w2s_hi[n * 256 + k] = __bfloat16_as_ushort(sh);
    g_w2s_lo[n * 256 + k] = __bfloat16_as_ushort(sl);
}

// ---------------- x rows 0..PAD1 -> bf16 hi/lo (k cols 0-127 of g_acat) -------
__global__ void xsplit_kernel(const float* __restrict__ x) {
    int idx = blockIdx.x * 256 + threadIdx.x;   // one thread per 8 floats
    int row = idx >> 4;                         // 16 threads per row
    int kc = (idx & 15) * 8;
    if (row >= PAD1) return;
    const float* ap = x + (size_t)row * IN_F + kc;
    float4 f0 = __ldg((const float4*)ap);
    float4 f1 = __ldg((const float4*)ap + 1);
    uint2 h0, l0, h1, l1;
    cvt4(f0, h0, l0);
    cvt4(f1, h1, l1);
    *(uint4*)(g_acat_hi + (size_t)row * 256 + kc) = make_uint4(h0.x, h0.y, h1.x, h1.y);
    *(uint4*)(g_acat_lo + (size_t)row * 256 + kc) = make_uint4(l0.x, l0.y, l1.x, l1.y);
}

// ---------------- layer-1 aggregation: one warp per dst row, MLP=8 ----------------
// Output written directly as bf16 hi/lo into g_acat cols 128-255.
template <typename IT>
__device__ __forceinline__ void agg1_body(const float* __restrict__ x,
                                          const IT* __restrict__ src,
                                          int row, int lane) {
    int s = g_off1[row], e = g_off1[row + 1];
    float ax = 0.f, ay = 0.f, az = 0.f, aw = 0.f;
    int i = s;
    for (; i + 8 <= e; i += 8) {            // 8 gathers in flight
        int sx[8];
        #pragma unroll
        for (int j = 0; j < 8; ++j) sx[j] = (int)__ldg(src + i + j);
        float4 v[8];
        #pragma unroll
        for (int j = 0; j < 8; ++j)
            v[j] = __ldg((const float4*)(x + (size_t)sx[j] * IN_F) + lane);
        #pragma unroll
        for (int j = 0; j < 8; ++j) {
            ax += v[j].x; ay += v[j].y; az += v[j].z; aw += v[j].w;
        }
    }
    for (; i + 2 <= e; i += 2) {
        int s0 = (int)__ldg(src + i), s1 = (int)__ldg(src + i + 1);
        float4 v0 = __ldg((const float4*)(x + (size_t)s0 * IN_F) + lane);
        float4 v1 = __ldg((const float4*)(x + (size_t)s1 * IN_F) + lane);
        ax += v0.x + v1.x; ay += v0.y + v1.y;
        az += v0.z + v1.z; aw += v0.w + v1.w;
    }
    if (i < e) {
        int s0 = (int)__ldg(src + i);
        float4 v0 = __ldg((const float4*)(x + (size_t)s0 * IN_F) + lane);
        ax += v0.x; ay += v0.y; az += v0.z; aw += v0.w;
    }
    int deg = e - s;
    float sc = 1.0f / (float)(deg > 0 ? deg : 1);
    uint2 h, l;
    cvt4(make_float4(ax * sc, ay * sc, az * sc, aw * sc), h, l);
    *(uint2*)(g_acat_hi + (size_t)row * 256 + 128 + lane * 4) = h;
    *(uint2*)(g_acat_lo + (size_t)row * 256 + 128 + lane * 4) = l;
}

__global__ __launch_bounds__(256) void agg1_kernel(const float* __restrict__ x,
                                                   const void* __restrict__ srcv) {
    int row = (blockIdx.x * 256 + threadIdx.x) >> 5;
    if (row >= N_DST1) return;
    int lane = threadIdx.x & 31;
    if (g_is64) agg1_body<long long>(x, (const long long*)srcv, row, lane);
    else        agg1_body<int>(x, (const int*)srcv, row, lane);
}

// ---------------- layer-1 GEMM: mma.sync + 4-stage cp.async pipeline ----------
// g_h[m,n] = relu( Acat[m,:] @ Wcat[:,n] + b1[n] ). All operands pre-split
// bf16 in global; zero in-kernel conversion. CTA 128m x 128n, 8 warps m32n64,
// K=256 in 16 chunks of 16. smem per stage: A 10240B + B 10240B; 4 stages.
#define G1_STAGE 10240
#define G1_SMEM  (8 * G1_STAGE)   // 81920 B

__global__ __launch_bounds__(256, 2) void gemm1_kernel(const float* __restrict__ bias1) {
    extern __shared__ __align__(16) unsigned short smem1[];

    const int tid = threadIdx.x, wid = tid >> 5, lane = tid & 31;
    const int bm = blockIdx.x * 128, bn = blockIdx.y * 128;
    const int wm = (wid >> 1) * 32, wn = (wid & 1) * 64;

    float acc[2][8][4];
    #pragma unroll
    for (int i = 0; i < 2; i++)
        #pragma unroll
        for (int j = 0; j < 8; j++)
            #pragma unroll
            for (int q = 0; q < 4; q++) acc[i][j][q] = 0.f;

    const int cr = tid >> 1;            // copy row (0..127)
    const int ck = (tid & 1) * 8;       // k offset 0 or 8

    const unsigned short* srcAh = g_acat_hi + (size_t)(bm + cr) * 256 + ck;
    const unsigned short* srcAl = g_acat_lo + (size_t)(bm + cr) * 256 + ck;
    const unsigned short* srcBh = g_bt_hi + (size_t)(bn + cr) * 256 + ck;
    const unsigned short* srcBl = g_bt_lo + (size_t)(bn + cr) * 256 + ck;

    const unsigned aBase = smem_u32(smem1);
    const unsigned bBase = aBase + 4 * G1_STAGE;
    const unsigned stOff = ((unsigned)cr * 40 + ck) * 2;   // within-stage store

    const int lr = lane & 15, lc = (lane >> 4) * 8;
    const unsigned offA = ((unsigned)(wm + lr) * 40 + lc) * 2;
    const unsigned offB = ((unsigned)(wn + lr) * 40 + lc) * 2;

    // prologue: stages 0..2 <- chunks 0..2
    #pragma unroll
    for (int c = 0; c < 3; ++c) {
        unsigned da = aBase + c * G1_STAGE + stOff;
        unsigned db = bBase + c * G1_STAGE + stOff;
        CP16(da,      srcAh + c * 16);
        CP16(da + 32, srcAl + c * 16);
        CP16(db,      srcBh + c * 16);
        CP16(db + 32, srcBl + c * 16);
        CP_COMMIT();
    }

    #pragma unroll 1
    for (int ch = 0; ch < 16; ++ch) {
        CP_WAIT2();
        __syncthreads();
        const int buf = ch & 3;
        {
            const unsigned aB = aBase + buf * G1_STAGE;
            const unsigned bB = bBase + buf * G1_STAGE;
            unsigned ah[2][4], al[2][4];
            #pragma unroll
            for (int mt = 0; mt < 2; ++mt) {
                ldsm_x4(ah[mt], aB + offA + mt * 1280);
                ldsm_x4(al[mt], aB + offA + mt * 1280 + 32);
            }
            #pragma unroll
            for (int nt2 = 0; nt2 < 4; ++nt2) {
                unsigned bh[4], bl[4];
                ldsm_x4(bh, bB + offB + nt2 * 1280);
                ldsm_x4(bl, bB + offB + nt2 * 1280 + 32);
                #pragma unroll
                for (int mt = 0; mt < 2; ++mt) {
                    float* c0 = acc[mt][nt2 * 2];
                    float* c1 = acc[mt][nt2 * 2 + 1];
                    mma_bf16(c0, ah[mt], bh[0], bh[2]);
                    mma_bf16(c0, ah[mt], bl[0], bl[2]);
                    mma_bf16(c0, al[mt], bh[0], bh[2]);
                    mma_bf16(c1, ah[mt], bh[1], bh[3]);
                    mma_bf16(c1, ah[mt], bl[1], bl[3]);
                    mma_bf16(c1, al[mt], bh[1], bh[3]);
                }
            }
        }
        if (ch + 3 < 16) {
            const int c = ch + 3;
            const int st = c & 3;       // == (ch-1)&3, consumers passed top sync
            unsigned da = aBase + st * G1_STAGE + stOff;
            unsigned db = bBase + st * G1_STAGE + stOff;
            CP16(da,      srcAh + c * 16);
            CP16(da + 32, srcAl + c * 16);
            CP16(db,      srcBh + c * 16);
            CP16(db + 32, srcBl + c * 16);
        }
        CP_COMMIT();                    // empty groups keep the count aligned
    }

    // epilogue: bias + relu -> g_h
    const int erow = lane >> 2;
    const int ecol = (lane & 3) * 2;
    #pragma unroll
    for (int nt = 0; nt < 8; ++nt) {
        const int col = bn + wn + nt * 8 + ecol;
        const float b0 = __ldg(bias1 + col);
        const float b1 = __ldg(bias1 + col + 1);
        #pragma unroll
        for (int mt = 0; mt < 2; ++mt) {
            const float* c = acc[mt][nt];
            const int r0 = bm + wm + mt * 16 + erow;
            float* p0 = g_h + (size_t)r0 * H_F + col;
            *(float2*)p0             = make_float2(fmaxf(c[0] + b0, 0.f), fmaxf(c[1] + b1, 0.f));
            *(float2*)(p0 + 8 * H_F) = make_float2(fmaxf(c[2] + b0, 0.f), fmaxf(c[3] + b1, 0.f));
        }
    }
}

// ---------------- layer-2 GEMMs on tensor cores: [128m, K=256] @ W2[256, 64] ----
// MODE 0: g_p[m, 0:48] = g_h[m,:] @ Wn2 (pad cols = 0)
// MODE 1: out[m, n<47] = g_h[m,:] @ Ws2 + g_pagg[m,n] + b2[n], m < N_DST2
template <int MODE>
__global__ __launch_bounds__(256, 2) void small_mma_kernel(
    const float* __restrict__ bias2, float* __restrict__ outp) {
    __shared__ __align__(16) unsigned short sA[2][128][40];
    __shared__ __align__(16) unsigned short sB[2][64][40];

    const unsigned short* wHi = (MODE == 0) ? g_w2n_hi : g_w2s_hi;
    const unsigned short* wLo = (MODE == 0) ? g_w2n_lo : g_w2s_lo;

    const int tid = threadIdx.x, wid = tid >> 5, lane = tid & 31;
    const int bm = blockIdx.x * 128;
    const int wm = wid * 16;

    float acc[8][4];
    #pragma unroll
    for (int j = 0; j < 8; j++)
        #pragma unroll
        for (int q = 0; q < 4; q++) acc[j][q] = 0.f;

    const int acr = tid >> 1;          // A conversion row 0..127
    const int ack = (tid & 1) * 8;     // k offset 0 or 8
    const int bcr = tid >> 2;          // B row 0..63
    const int bck = (tid & 3) * 4;     // k offset 0,4,8,12

    const unsigned aBase = smem_u32(&sA[0][0][0]);
    const unsigned bBase = smem_u32(&sB[0][0][0]);
    const int lr = lane & 15, lc = (lane >> 4) * 8;
    const unsigned offA = ((unsigned)(wm + lr) * 40 + lc) * 2;
    const unsigned offB = ((unsigned)lr * 40 + lc) * 2;

    // prologue: chunk 0
    float4 fa0, fa1; uint2 qbh, qbl;
    {
        const float* ap = g_h + (size_t)(bm + acr) * H_F + ack;
        fa0 = __ldg((const float4*)ap);
        fa1 = __ldg((const float4*)ap + 1);
        qbh = *(const uint2*)(wHi + (size_t)bcr * 256 + bck);
        qbl = *(const uint2*)(wLo + (size_t)bcr * 256 + bck);
    }
    {
        uint2 h0, l0, h1, l1;
        cvt4(fa0, h0, l0);
        cvt4(fa1, h1, l1);
        *(uint4*)&sA[0][acr][ack]      = make_uint4(h0.x, h0.y, h1.x, h1.y);
        *(uint4*)&sA[0][acr][16 + ack] = make_uint4(l0.x, l0.y, l1.x, l1.y);
        *(uint2*)&sB[0][bcr][bck]      = qbh;
        *(uint2*)&sB[0][bcr][16 + bck] = qbl;
    }
    __syncthreads();

    #pragma unroll 1
    for (int ch = 0; ch < 16; ++ch) {
        const int buf = ch & 1;
        if (ch < 15) {
            const int kc = (ch + 1) * 16;
            const float* ap = g_h + (size_t)(bm + acr) * H_F + kc + ack;
            fa0 = __ldg((const float4*)ap);
            fa1 = __ldg((const float4*)ap + 1);
            qbh = *(const uint2*)(wHi + (size_t)bcr * 256 + kc + bck);
            qbl = *(const uint2*)(wLo + (size_t)bcr * 256 + kc + bck);
        }
        {
            const unsigned aB = aBase + buf * (128 * 40 * 2);
            const unsigned bB = bBase + buf * (64 * 40 * 2);
            unsigned ah[4], al[4];
            ldsm_x4(ah, aB + offA);
            ldsm_x4(al, aB + offA + 32);
            #pragma unroll
            for (int nt2 = 0; nt2 < 4; ++nt2) {
                unsigned bh[4], bl[4];
                ldsm_x4(bh, bB + offB + nt2 * 1280);
                ldsm_x4(bl, bB + offB + nt2 * 1280 + 32);
                float* c0 = acc[nt2 * 2];
                float* c1 = acc[nt2 * 2 + 1];
                mma_bf16(c0, ah, bh[0], bh[2]);
                mma_bf16(c0, ah, bl[0], bl[2]);
                mma_bf16(c0, al, bh[0], bh[2]);
                mma_bf16(c1, ah, bh[1], bh[3]);
                mma_bf16(c1, ah, bl[1], bl[3]);
                mma_bf16(c1, al, bh[1], bh[3]);
            }
        }
        if (ch < 15) {
            const int nb = buf ^ 1;
            uint2 h0, l0, h1, l1;
            cvt4(fa0, h0, l0);
            cvt4(fa1, h1, l1);
            *(uint4*)&sA[nb][acr][ack]      = make_uint4(h0.x, h0.y, h1.x, h1.y);
            *(uint4*)&sA[nb][acr][16 + ack] = make_uint4(l0.x, l0.y, l1.x, l1.y);
            *(uint2*)&sB[nb][bcr][bck]      = qbh;
            *(uint2*)&sB[nb][bcr][16 + bck] = qbl;
            __syncthreads();
        }
    }

    // epilogue
    const int erow = lane >> 2;
    const int ecol = (lane & 3) * 2;
    #pragma unroll
    for (int nt = 0; nt < 8; ++nt) {
        const int col = nt * 8 + ecol;
        const float* c = acc[nt];
        const int r0 = bm + wm + erow;
        const int r1 = r0 + 8;
        if (MODE == 0) {
            if (col < PN) {
                *(float2*)(g_p + (size_t)r0 * PN + col) = make_float2(c[0], c[1]);
                *(float2*)(g_p + (size_t)r1 * PN + col) = make_float2(c[2], c[3]);
            }
        } else {
            if (col < N_CLS) {
                const float b0 = __ldg(bias2 + col);
                if (r0 < N_DST2)
                    outp[r0 * N_CLS + col] = c[0] + g_pagg[(size_t)r0 * PN + col] + b0;
                if (r1 < N_DST2)
                    outp[r1 * N_CLS + col] = c[2] + g_pagg[(size_t)r1 * PN + col] + b0;
                if (col + 1 < N_CLS) {
                    const float b1 = __ldg(bias2 + col + 1);
                    if (r0 < N_DST2)
                        outp[r0 * N_CLS + col + 1] =
                            c[1] + g_pagg[(size_t)r0 * PN + col + 1] + b1;
                    if (r1 < N_DST2)
                        outp[r1 * N_CLS + col + 1] =
                            c[3] + g_pagg[(size_t)r1 * PN + col + 1] + b1;
                }
            }
        }
    }
}

// ---------------- layer-2 aggregation over projected feats (48 wide) ----------------
template <typename IT>
__device__ __forceinline__ void aggp_body(const IT* __restrict__ src, int g, int t) {
    int s = g_off2[g], e = g_off2[g + 1];
    bool act = (t < PN);
    size_t to = t;
    float acc = 0.f;
    int i = s;
    for (; i + 4 <= e; i += 4) {
        int s0 = (int)__ldg(src + i),     s1 = (int)__ldg(src + i + 1);
        int s2 = (int)__ldg(src + i + 2), s3 = (int)__ldg(src + i + 3);
        if (act) {
            float v0 = __ldg((const float*)g_p + (size_t)s0 * PN + to);
            float v1 = __ldg((const float*)g_p + (size_t)s1 * PN + to);
            float v2 = __ldg((const float*)g_p + (size_t)s2 * PN + to);
            float v3 = __ldg((const float*)g_p + (size_t)s3 * PN + to);
            acc += (v0 + v1) + (v2 + v3);
        }
    }
    for (; i < e; ++i) {
        int s0 = (int)__ldg(src + i);
        if (act) acc += __ldg((const float*)g_p + (size_t)s0 * PN + to);
    }
    int deg = e - s;
    float sc = 1.0f / (float)(deg > 0 ? deg : 1);
    if (act) g_pagg[(size_t)g * PN + t] = acc * sc;
}

__global__ __launch_bounds__(256) void aggp_kernel(const void* __restrict__ srcv) {
    int g = (blockIdx.x * 256 + threadIdx.x) >> 6;
    if (g >= N_DST2) return;
    int t = threadIdx.x & 63;
    if (g_is64) aggp_body<long long>((const long long*)srcv, g, t);
    else        aggp_body<int>((const int*)srcv, g, t);
}

// ---------------- launch ----------------
extern "C" void kernel_launch(void* const* d_in, const int* in_sizes, int n_in,
                              void* d_out, int out_size) {
    const float* x       = (const float*)d_in[0];
    const float* Wself1  = (const float*)d_in[1];
    const float* Wneigh1 = (const float*)d_in[2];
    const float* b1      = (const float*)d_in[3];
    const float* Wself2  = (const float*)d_in[4];
    const float* Wneigh2 = (const float*)d_in[5];
    const float* b2      = (const float*)d_in[6];
    const void*  src1    = d_in[7];
    const void*  dst1    = d_in[8];
    const void*  src2    = d_in[9];
    const void*  dst2    = d_in[10];
    float* out = (float*)d_out;

    cudaFuncSetAttribute(gemm1_kernel,
                         cudaFuncAttributeMaxDynamicSharedMemorySize, G1_SMEM);

    detect_kernel<<<1, 32>>>((const int*)src1);
    offsets_kernel<<<(E1 / 4 + 255) / 256, 256>>>(dst1, dst2);
    wsplit_kernel<<<256, 256>>>(Wself1, Wneigh1);
    {
        dim3 gw2(64, 4);
        wsplit2_kernel<<<gw2, 64>>>(Wneigh2, Wself2);
    }
    xsplit_kernel<<<PAD1 * 16 / 256, 256>>>(x);

    agg1_kernel<<<(N_DST1 + 7) / 8, 256>>>(x, src1);

    dim3 g1(PAD1 / 128, 2);             // 391 x 2 blocks
    gemm1_kernel<<<g1, 256, G1_SMEM>>>(b1);

    small_mma_kernel<0><<<PAD1 / 128, 256>>>(nullptr, nullptr);     // p = h @ Wn2

    aggp_kernel<<<(N_DST2 * 64) / 256, 256>>>(src2);

    small_mma_kernel<1><<<(N_DST2 + 127) / 128, 256>>>(b2, out);    // out
}

// round 17
// speedup vs baseline: 1.0791x; 1.0791x over previous
#include <cuda_runtime.h>
#include <cuda_bf16.h>

// ---------------- problem constants (fixed shapes) ----------------
#define N_SRC1 200000
#define N_DST1 50000
#define N_DST2 10000
#define E1     2000000
#define E2     400000
#define IN_F   128
#define H_F    256
#define N_CLS  47

#define PAD1   50048   // N_DST1 padded to multiple of 128
#define PN     48      // padded layer-2 projected width

// ---------------- scratch (device globals; zero-initialized) ----------------
__device__ int   g_is64;
__device__ int   g_off1[N_DST1 + 1];
__device__ int   g_off2[N_DST2 + 1];
__device__ float g_hneigh1[(size_t)PAD1 * IN_F];   // layer1 mean-aggregated feats
__device__ float g_h[(size_t)PAD1 * H_F];          // layer1 output (relu'd)
__device__ float g_p[(size_t)PAD1 * PN];           // h @ Wneigh2 (projected, padded)
__device__ float g_pagg[(size_t)N_DST2 * PN];      // mean-aggregated p
// layer-1 W concat transposed to [n=256][k=256], bf16 hi/lo
__device__ __align__(16) unsigned short g_bt_hi[256 * 256];
__device__ __align__(16) unsigned short g_bt_lo[256 * 256];
// layer-2 weights transposed to [n=64 pad][k=256], bf16 hi/lo
__device__ __align__(16) unsigned short g_w2n_hi[64 * 256];
__device__ __align__(16) unsigned short g_w2n_lo[64 * 256];
__device__ __align__(16) unsigned short g_w2s_hi[64 * 256];
__device__ __align__(16) unsigned short g_w2s_lo[64 * 256];

// ---------------- helpers ----------------
__device__ __forceinline__ unsigned smem_u32(const void* p) {
    unsigned a;
    asm("{ .reg .u64 t; cvta.to.shared.u64 t, %1; cvt.u32.u64 %0, t; }"
        : "=r"(a) : "l"(p));
    return a;
}
__device__ __forceinline__ void ldsm_x4(unsigned* r, unsigned addr) {
    asm volatile("ldmatrix.sync.aligned.m8n8.x4.shared.b16 {%0,%1,%2,%3}, [%4];"
                 : "=r"(r[0]), "=r"(r[1]), "=r"(r[2]), "=r"(r[3]) : "r"(addr));
}
__device__ __forceinline__ void mma_bf16(float* c, const unsigned* a,
                                         unsigned b0, unsigned b1) {
    asm volatile(
        "mma.sync.aligned.m16n8k16.row.col.f32.bf16.bf16.f32 "
        "{%0,%1,%2,%3}, {%4,%5,%6,%7}, {%8,%9}, {%0,%1,%2,%3};"
        : "+f"(c[0]), "+f"(c[1]), "+f"(c[2]), "+f"(c[3])
        : "r"(a[0]), "r"(a[1]), "r"(a[2]), "r"(a[3]), "r"(b0), "r"(b1));
}
__device__ __forceinline__ void cvt4(const float4& f, uint2& h, uint2& l) {
    __nv_bfloat16 h0 = __float2bfloat16(f.x), h1 = __float2bfloat16(f.y);
    __nv_bfloat16 h2 = __float2bfloat16(f.z), h3 = __float2bfloat16(f.w);
    __nv_bfloat16 l0 = __float2bfloat16(f.x - __bfloat162float(h0));
    __nv_bfloat16 l1 = __float2bfloat16(f.y - __bfloat162float(h1));
    __nv_bfloat16 l2 = __float2bfloat16(f.z - __bfloat162float(h2));
    __nv_bfloat16 l3 = __float2bfloat16(f.w - __bfloat162float(h3));
    h.x = (unsigned)__bfloat16_as_ushort(h0) | ((unsigned)__bfloat16_as_ushort(h1) << 16);
    h.y = (unsigned)__bfloat16_as_ushort(h2) | ((unsigned)__bfloat16_as_ushort(h3) << 16);
    l.x = (unsigned)__bfloat16_as_ushort(l0) | ((unsigned)__bfloat16_as_ushort(l1) << 16);
    l.y = (unsigned)__bfloat16_as_ushort(l2) | ((unsigned)__bfloat16_as_ushort(l3) << 16);
}

// ---------------- fused prep: wsplit (b<256) + wsplit2 (256..319) + detect (320)
__global__ void prep_kernel(const float* __restrict__ Ws, const float* __restrict__ Wn,
                            const float* __restrict__ Wn2, const float* __restrict__ Ws2,
                            const int* __restrict__ src1_raw) {
    int b = blockIdx.x;
    int t = threadIdx.x;
    if (b < 256) {
        // layer-1 W concat transpose + split; n = b, k = t
        float v = (t < 128) ? Ws[t * H_F + b] : Wn[(t - 128) * H_F + b];
        __nv_bfloat16 hb = __float2bfloat16(v);
        __nv_bfloat16 lb = __float2bfloat16(v - __bfloat162float(hb));
        g_bt_hi[b * 256 + t] = __bfloat16_as_ushort(hb);
        g_bt_lo[b * 256 + t] = __bfloat16_as_ushort(lb);
    } else if (b < 320) {
        int n = b - 256;                 // 0..63 (pad cols 47..63 -> 0)
        float vn = (n < N_CLS) ? Wn2[t * N_CLS + n] : 0.f;
        float vs = (n < N_CLS) ? Ws2[t * N_CLS + n] : 0.f;
        __nv_bfloat16 nh = __float2bfloat16(vn);
        __nv_bfloat16 nl = __float2bfloat16(vn - __bfloat162float(nh));
        __nv_bfloat16 sh = __float2bfloat16(vs);
        __nv_bfloat16 sl = __float2bfloat16(vs - __bfloat162float(sh));
        g_w2n_hi[n * 256 + t] = __bfloat16_as_ushort(nh);
        g_w2n_lo[n * 256 + t] = __bfloat16_as_ushort(nl);
        g_w2s_hi[n * 256 + t] = __bfloat16_as_ushort(sh);
        g_w2s_lo[n * 256 + t] = __bfloat16_as_ushort(sl);
    } else if (t == 0) {
        // index dtype detection: src1 uniform-random in [0, 200000); if int64,
        // every odd 32-bit word is zero; if int32, essentially surely nonzero.
        int nz = 0;
        for (int i = 1; i < 256; i += 2) nz |= (src1_raw[i] != 0);
        g_is64 = nz ? 0 : 1;
    }
}

// ---------------- CSR offsets via boundary scatter, 4 edges/thread ----------------
__device__ __forceinline__ void scatter4(const void* dst, int* off, int E,
                                         int ndst, int i, int is64) {
    int base = i * 4;
    int p;
    if (is64) p = (base == 0) ? -1 : (int)((const long long*)dst)[base - 1];
    else      p = (base == 0) ? -1 : ((const int*)dst)[base - 1];
    #pragma unroll
    for (int j = 0; j < 4; ++j) {
        int d = is64 ? (int)((const long long*)dst)[base + j]
                     : ((const int*)dst)[base + j];
        for (int t = p + 1; t <= d; ++t) off[t] = base + j;
        p = d;
    }
    if (base + 4 == E)
        for (int t = p + 1; t <= ndst; ++t) off[t] = E;
}

__global__ void offsets_kernel(const void* __restrict__ dst1,
                               const void* __restrict__ dst2) {
    int i = blockIdx.x * blockDim.x + threadIdx.x;   // E1/4 and E2/4 are exact
    int is64 = g_is64;
    if (i < E1 / 4) scatter4(dst1, g_off1, E1, N_DST1, i, is64);
    if (i < E2 / 4) scatter4(dst2, g_off2, E2, N_DST2, i, is64);
}

// ---------------- layer-1 aggregation: one warp per dst row, MLP=4 ----------------
// Output stores use .cs (evict-first) so the 25.6 MB of writes don't evict x
// from L2 (x is 102 MB vs 126 MB L2; keeping it resident cuts DRAM refetch).
template <typename IT>
__device__ __forceinline__ void agg1_body(const float* __restrict__ x,
                                          const IT* __restrict__ src,
                                          int row, int lane) {
    int s = g_off1[row], e = g_off1[row + 1];
    float ax = 0.f, ay = 0.f, az = 0.f, aw = 0.f;
    int i = s;
    for (; i + 4 <= e; i += 4) {            // 4 gathers in flight
        int s0 = (int)__ldg(src + i),     s1 = (int)__ldg(src + i + 1);
        int s2 = (int)__ldg(src + i + 2), s3 = (int)__ldg(src + i + 3);
        float4 v0 = __ldg((const float4*)(x + (size_t)s0 * IN_F) + lane);
        float4 v1 = __ldg((const float4*)(x + (size_t)s1 * IN_F) + lane);
        float4 v2 = __ldg((const float4*)(x + (size_t)s2 * IN_F) + lane);
        float4 v3 = __ldg((const float4*)(x + (size_t)s3 * IN_F) + lane);
        ax += (v0.x + v1.x) + (v2.x + v3.x);
        ay += (v0.y + v1.y) + (v2.y + v3.y);
        az += (v0.z + v1.z) + (v2.z + v3.z);
        aw += (v0.w + v1.w) + (v2.w + v3.w);
    }
    for (; i < e; ++i) {
        int s0 = (int)__ldg(src + i);
        float4 v0 = __ldg((const float4*)(x + (size_t)s0 * IN_F) + lane);
        ax += v0.x; ay += v0.y; az += v0.z; aw += v0.w;
    }
    int deg = e - s;
    float sc = 1.0f / (float)(deg > 0 ? deg : 1);
    __stcs((float4*)(g_hneigh1 + (size_t)row * IN_F) + lane,
           make_float4(ax * sc, ay * sc, az * sc, aw * sc));
}

__global__ __launch_bounds__(256) void agg1_kernel(const float* __restrict__ x,
                                                   const void* __restrict__ srcv) {
    int row = (blockIdx.x * 256 + threadIdx.x) >> 5;
    if (row >= N_DST1) return;
    int lane = threadIdx.x & 31;
    if (g_is64) agg1_body<long long>(x, (const long long*)srcv, row, lane);
    else        agg1_body<int>(x, (const int*)srcv, row, lane);
}

// ---------------- layer-1 GEMM on tensor cores (mma.sync, bf16 3-term split) --
// g_h[m,n] = relu( Acat[m,:] @ Wcat[:,n] + b1[n] ),  Acat = [x | hneigh1].
// Per CTA: 128m x 128n, 8 warps each m32 x n64, K in 16 chunks of 16. (R13/R15)
__global__ __launch_bounds__(256, 2) void gemm1_kernel(
    const float* __restrict__ x, const float* __restrict__ bias1) {
    __shared__ __align__(16) unsigned short sA[2][128][40];
    __shared__ __align__(16) unsigned short sB[2][128][40];

    const int tid = threadIdx.x, wid = tid >> 5, lane = tid & 31;
    const int bm = blockIdx.x * 128, bn = blockIdx.y * 128;
    const int wm = (wid >> 1) * 32, wn = (wid & 1) * 64;

    float acc[2][8][4];
    #pragma unroll
    for (int i = 0; i < 2; i++)
        #pragma unroll
        for (int j = 0; j < 8; j++)
            #pragma unroll
            for (int q = 0; q < 4; q++) acc[i][j][q] = 0.f;

    const int cr = tid >> 1;            // conversion row / B n-row (0..127)
    const int ck = (tid & 1) * 8;       // k offset 0 or 8

    const unsigned aBase = smem_u32(&sA[0][0][0]);
    const unsigned bBase = smem_u32(&sB[0][0][0]);
    const int lr = lane & 15, lc = (lane >> 4) * 8;
    const unsigned offA = ((unsigned)(wm + lr) * 40 + lc) * 2;
    const unsigned offB = ((unsigned)(wn + lr) * 40 + lc) * 2;

    // prologue: chunk 0 -> regs -> buf 0
    float4 fa0, fa1; uint4 pbh, pbl;
    {
        const float* ap = x + (size_t)(bm + cr) * IN_F + ck;
        fa0 = __ldg((const float4*)ap);
        fa1 = __ldg((const float4*)ap + 1);
        const size_t bo = (size_t)(bn + cr) * 256 + ck;
        pbh = *(const uint4*)(g_bt_hi + bo);
        pbl = *(const uint4*)(g_bt_lo + bo);
    }
    {
        uint2 h0, l0, h1, l1;
        cvt4(fa0, h0, l0);
        cvt4(fa1, h1, l1);
        *(uint4*)&sA[0][cr][ck]      = make_uint4(h0.x, h0.y, h1.x, h1.y);
        *(uint4*)&sA[0][cr][16 + ck] = make_uint4(l0.x, l0.y, l1.x, l1.y);
        *(uint4*)&sB[0][cr][ck]      = pbh;
        *(uint4*)&sB[0][cr][16 + ck] = pbl;
    }
    __syncthreads();

    #pragma unroll 1
    for (int ch = 0; ch < 16; ++ch) {
        const int buf = ch & 1;
        if (ch < 15) {
            const int chn = ch + 1;
            const float* Asel = (chn < 8) ? x : g_hneigh1;
            const int kc = (chn & 7) * 16;
            const float* ap = Asel + (size_t)(bm + cr) * IN_F + kc + ck;
            fa0 = __ldg((const float4*)ap);
            fa1 = __ldg((const float4*)ap + 1);
            const size_t bo = (size_t)(bn + cr) * 256 + chn * 16 + ck;
            pbh = *(const uint4*)(g_bt_hi + bo);
            pbl = *(const uint4*)(g_bt_lo + bo);
        }
        {
            const unsigned aB = aBase + buf * 10240;
            const unsigned bB = bBase + buf * 10240;
            unsigned ah[2][4], al[2][4];
            #pragma unroll
            for (int mt = 0; mt < 2; ++mt) {
                ldsm_x4(ah[mt], aB + offA + mt * 1280);
                ldsm_x4(al[mt], aB + offA + mt * 1280 + 32);
            }
            #pragma unroll
            for (int nt2 = 0; nt2 < 4; ++nt2) {
                unsigned bh[4], bl[4];
                ldsm_x4(bh, bB + offB + nt2 * 1280);
                ldsm_x4(bl, bB + offB + nt2 * 1280 + 32);
                #pragma unroll
                for (int mt = 0; mt < 2; ++mt) {
                    float* c0 = acc[mt][nt2 * 2];
                    float* c1 = acc[mt][nt2 * 2 + 1];
                    mma_bf16(c0, ah[mt], bh[0], bh[2]);
                    mma_bf16(c0, ah[mt], bl[0], bl[2]);
                    mma_bf16(c0, al[mt], bh[0], bh[2]);
                    mma_bf16(c1, ah[mt], bh[1], bh[3]);
                    mma_bf16(c1, ah[mt], bl[1], bl[3]);
                    mma_bf16(c1, al[mt], bh[1], bh[3]);
                }
            }
        }
        if (ch < 15) {
            const int nb = buf ^ 1;
            uint2 h0, l0, h1, l1;
            cvt4(fa0, h0, l0);
            cvt4(fa1, h1, l1);
            *(uint4*)&sA[nb][cr][ck]      = make_uint4(h0.x, h0.y, h1.x, h1.y);
            *(uint4*)&sA[nb][cr][16 + ck] = make_uint4(l0.x, l0.y, l1.x, l1.y);
            *(uint4*)&sB[nb][cr][ck]      = pbh;
            *(uint4*)&sB[nb][cr][16 + ck] = pbl;
            __syncthreads();
        }
    }

    // epilogue: bias + relu -> g_h
    const int erow = lane >> 2;
    const int ecol = (lane & 3) * 2;
    #pragma unroll
    for (int nt = 0; nt < 8; ++nt) {
        const int col = bn + wn + nt * 8 + ecol;
        const float b0 = __ldg(bias1 + col);
        const float b1 = __ldg(bias1 + col + 1);
        #pragma unroll
        for (int mt = 0; mt < 2; ++mt) {
            const float* c = acc[mt][nt];
            const int r0 = bm + wm + mt * 16 + erow;
            float* p0 = g_h + (size_t)r0 * H_F + col;
            *(float2*)p0             = make_float2(fmaxf(c[0] + b0, 0.f), fmaxf(c[1] + b1, 0.f));
            *(float2*)(p0 + 8 * H_F) = make_float2(fmaxf(c[2] + b0, 0.f), fmaxf(c[3] + b1, 0.f));
        }
    }
}

// ---------------- layer-2 GEMMs on tensor cores: [128m, K=256] @ W2[256, 64] ----
// MODE 0: g_p[m, 0:48] = g_h[m,:] @ Wn2 (pad cols = 0)
// MODE 1: out[m, n<47] = g_h[m,:] @ Ws2 + g_pagg[m,n] + b2[n], m < N_DST2
template <int MODE>
__global__ __launch_bounds__(256, 2) void small_mma_kernel(
    const float* __restrict__ bias2, float* __restrict__ outp) {
    __shared__ __align__(16) unsigned short sA[2][128][40];
    __shared__ __align__(16) unsigned short sB[2][64][40];

    const unsigned short* wHi = (MODE == 0) ? g_w2n_hi : g_w2s_hi;
    const unsigned short* wLo = (MODE == 0) ? g_w2n_lo : g_w2s_lo;

    const int tid = threadIdx.x, wid = tid >> 5, lane = tid & 31;
    const int bm = blockIdx.x * 128;
    const int wm = wid * 16;

    float acc[8][4];
    #pragma unroll
    for (int j = 0; j < 8; j++)
        #pragma unroll
        for (int q = 0; q < 4; q++) acc[j][q] = 0.f;

    const int acr = tid >> 1;          // A conversion row 0..127
    const int ack = (tid & 1) * 8;     // k offset 0 or 8
    const int bcr = tid >> 2;          // B row 0..63
    const int bck = (tid & 3) * 4;     // k offset 0,4,8,12

    const unsigned aBase = smem_u32(&sA[0][0][0]);
    const unsigned bBase = smem_u32(&sB[0][0][0]);
    const int lr = lane & 15, lc = (lane >> 4) * 8;
    const unsigned offA = ((unsigned)(wm + lr) * 40 + lc) * 2;
    const unsigned offB = ((unsigned)lr * 40 + lc) * 2;

    // prologue: chunk 0
    float4 fa0, fa1; uint2 qbh, qbl;
    {
        const float* ap = g_h + (size_t)(bm + acr) * H_F + ack;
        fa0 = __ldg((const float4*)ap);
        fa1 = __ldg((const float4*)ap + 1);
        qbh = *(const uint2*)(wHi + (size_t)bcr * 256 + bck);
        qbl = *(const uint2*)(wLo + (size_t)bcr * 256 + bck);
    }
    {
        uint2 h0, l0, h1, l1;
        cvt4(fa0, h0, l0);
        cvt4(fa1, h1, l1);
        *(uint4*)&sA[0][acr][ack]      = make_uint4(h0.x, h0.y, h1.x, h1.y);
        *(uint4*)&sA[0][acr][16 + ack] = make_uint4(l0.x, l0.y, l1.x, l1.y);
        *(uint2*)&sB[0][bcr][bck]      = qbh;
        *(uint2*)&sB[0][bcr][16 + bck] = qbl;
    }
    __syncthreads();

    #pragma unroll 1
    for (int ch = 0; ch < 16; ++ch) {
        const int buf = ch & 1;
        if (ch < 15) {
            const int kc = (ch + 1) * 16;
            const float* ap = g_h + (size_t)(bm + acr) * H_F + kc + ack;
            fa0 = __ldg((const float4*)ap);
            fa1 = __ldg((const float4*)ap + 1);
            qbh = *(const uint2*)(wHi + (size_t)bcr * 256 + kc + bck);
            qbl = *(const uint2*)(wLo + (size_t)bcr * 256 + kc + bck);
        }
        {
            const unsigned aB = aBase + buf * (128 * 40 * 2);
            const unsigned bB = bBase + buf * (64 * 40 * 2);
            unsigned ah[4], al[4];
            ldsm_x4(ah, aB + offA);
            ldsm_x4(al, aB + offA + 32);
            #pragma unroll
            for (int nt2 = 0; nt2 < 4; ++nt2) {
                unsigned bh[4], bl[4];
                ldsm_x4(bh, bB + offB + nt2 * 1280);
                ldsm_x4(bl, bB + offB + nt2 * 1280 + 32);
                float* c0 = acc[nt2 * 2];
                float* c1 = acc[nt2 * 2 + 1];
                mma_bf16(c0, ah, bh[0], bh[2]);
                mma_bf16(c0, ah, bl[0], bl[2]);
                mma_bf16(c0, al, bh[0], bh[2]);
                mma_bf16(c1, ah, bh[1], bh[3]);
                mma_bf16(c1, ah, bl[1], bl[3]);
                mma_bf16(c1, al, bh[1], bh[3]);
            }
        }
        if (ch < 15) {
            const int nb = buf ^ 1;
            uint2 h0, l0, h1, l1;
            cvt4(fa0, h0, l0);
            cvt4(fa1, h1, l1);
            *(uint4*)&sA[nb][acr][ack]      = make_uint4(h0.x, h0.y, h1.x, h1.y);
            *(uint4*)&sA[nb][acr][16 + ack] = make_uint4(l0.x, l0.y, l1.x, l1.y);
            *(uint2*)&sB[nb][bcr][bck]      = qbh;
            *(uint2*)&sB[nb][bcr][16 + bck] = qbl;
            __syncthreads();
        }
    }

    // epilogue
    const int erow = lane >> 2;
    const int ecol = (lane & 3) * 2;
    #pragma unroll
    for (int nt = 0; nt < 8; ++nt) {
        const int col = nt * 8 + ecol;
        const float* c = acc[nt];
        const int r0 = bm + wm + erow;
        const int r1 = r0 + 8;
        if (MODE == 0) {
            if (col < PN) {
                *(float2*)(g_p + (size_t)r0 * PN + col) = make_float2(c[0], c[1]);
                *(float2*)(g_p + (size_t)r1 * PN + col) = make_float2(c[2], c[3]);
            }
        } else {
            if (col < N_CLS) {
                const float b0 = __ldg(bias2 + col);
                if (r0 < N_DST2)
                    outp[r0 * N_CLS + col] = c[0] + g_pagg[(size_t)r0 * PN + col] + b0;
                if (r1 < N_DST2)
                    outp[r1 * N_CLS + col] = c[2] + g_pagg[(size_t)r1 * PN + col] + b0;
                if (col + 1 < N_CLS) {
                    const float b1 = __ldg(bias2 + col + 1);
                    if (r0 < N_DST2)
                        outp[r0 * N_CLS + col + 1] =
                            c[1] + g_pagg[(size_t)r0 * PN + col + 1] + b1;
                    if (r1 < N_DST2)
                        outp[r1 * N_CLS + col + 1] =
                            c[3] + g_pagg[(size_t)r1 * PN + col + 1] + b1;
                }
            }
        }
    }
}

// ---------------- layer-2 aggregation over projected feats (48 wide) ----------------
// 16 threads/row, 12 active, float4 per thread (vs 48 scalar lanes before).
template <typename IT>
__device__ __forceinline__ void aggp_body(const IT* __restrict__ src, int g, int t) {
    int s = g_off2[g], e = g_off2[g + 1];
    bool act = (t < 12);
    size_t to = (size_t)t * 4;
    float4 a = make_float4(0.f, 0.f, 0.f, 0.f);
    int i = s;
    for (; i + 4 <= e; i += 4) {
        int s0 = (int)__ldg(src + i),     s1 = (int)__ldg(src + i + 1);
        int s2 = (int)__ldg(src + i + 2), s3 = (int)__ldg(src + i + 3);
        if (act) {
            float4 v0 = __ldg((const float4*)(g_p + (size_t)s0 * PN + to));
            float4 v1 = __ldg((const float4*)(g_p + (size_t)s1 * PN + to));
            float4 v2 = __ldg((const float4*)(g_p + (size_t)s2 * PN + to));
            float4 v3 = __ldg((const float4*)(g_p + (size_t)s3 * PN + to));
            a.x += (v0.x + v1.x) + (v2.x + v3.x);
            a.y += (v0.y + v1.y) + (v2.y + v3.y);
            a.z += (v0.z + v1.z) + (v2.z + v3.z);
            a.w += (v0.w + v1.w) + (v2.w + v3.w);
        }
    }
    for (; i < e; ++i) {
        int s0 = (int)__ldg(src + i);
        if (act) {
            float4 v0 = __ldg((const float4*)(g_p + (size_t)s0 * PN + to));
            a.x += v0.x; a.y += v0.y; a.z += v0.z; a.w += v0.w;
        }
    }
    int deg = e - s;
    float sc = 1.0f / (float)(deg > 0 ? deg : 1);
    if (act)
        __stcs((float4*)(g_pagg + (size_t)g * PN + to),
               make_float4(a.x * sc, a.y * sc, a.z * sc, a.w * sc));
}

__global__ __launch_bounds__(256) void aggp_kernel(const void* __restrict__ srcv) {
    int g = (blockIdx.x * 256 + threadIdx.x) >> 4;
    if (g >= N_DST2) return;
    int t = threadIdx.x & 15;
    if (g_is64) aggp_body<long long>((const long long*)srcv, g, t);
    else        aggp_body<int>((const int*)srcv, g, t);
}

// ---------------- launch ----------------
extern "C" void kernel_launch(void* const* d_in, const int* in_sizes, int n_in,
                              void* d_out, int out_size) {
    const float* x       = (const float*)d_in[0];
    const float* Wself1  = (const float*)d_in[1];
    const float* Wneigh1 = (const float*)d_in[2];
    const float* b1      = (const float*)d_in[3];
    const float* Wself2  = (const float*)d_in[4];
    const float* Wneigh2 = (const float*)d_in[5];
    const float* b2      = (const float*)d_in[6];
    const void*  src1    = d_in[7];
    const void*  dst1    = d_in[8];
    const void*  src2    = d_in[9];
    const void*  dst2    = d_in[10];
    float* out = (float*)d_out;

    prep_kernel<<<321, 256>>>(Wself1, Wneigh1, Wneigh2, Wself2, (const int*)src1);

    offsets_kernel<<<(E1 / 4 + 255) / 256, 256>>>(dst1, dst2);

    agg1_kernel<<<(N_DST1 + 7) / 8, 256>>>(x, src1);

    dim3 g1(PAD1 / 128, 2);             // 391 x 2 blocks
    gemm1_kernel<<<g1, 256>>>(x, b1);

    small_mma_kernel<0><<<PAD1 / 128, 256>>>(nullptr, nullptr);     // p = h @ Wn2

    aggp_kernel<<<(N_DST2 * 16) / 256, 256>>>(src2);

    small_mma_kernel<1><<<(N_DST2 + 127) / 128, 256>>>(b2, out);    // out
}